// round 13
// baseline (speedup 1.0000x reference)
#include <cuda_runtime.h>
#include <cuda_bf16.h>
#include <math.h>

// ---------------- problem constants ----------------
constexpr int Bv   = 8;      // videos
constexpr int Cc   = 256;    // feature dim
constexpr int Nn   = 128;    // N
constexpr int NNe  = Nn*Nn;  // 16384
constexpr int Sv   = 32;     // sentences
constexpr int Mv   = 64;     // moments
constexpr int Pn   = 8256;   // N*(N+1)/2 proposals
constexpr int BP   = Bv*Pn;  // 66048
constexpr int RT   = 128;    // pos rows = M*K
constexpr int NT2  = BP/32;  // 2064 GEMM column tiles (32 | Pn)
constexpr int PW   = 2*NT2;  // partial row width (2 N-halves per tile)
constexpr int GRID = 296;    // persistent GEMM CTAs (2 per SM x 148)

// ---------------- scratch ----------------
__device__ __align__(16) int            g_flat[Pn];
__device__ __align__(16) float          g_inv[BP];
__device__ __align__(16) __nv_bfloat16  g_vfb[(size_t)BP*Cc];
__device__ __align__(16) unsigned char  g_iou[Sv*Pn];
__device__ __align__(16) float          g_cv[Mv*16];
__device__ __align__(16) int            g_ci[Mv*16];
__device__ __align__(16) unsigned       g_posfr[RT*128];      // A in mma-fragment-major layout
__device__ __align__(16) float          g_posf[RT*Cc];
__device__ __align__(16) float          g_partial[(size_t)RT*PW];  // [row][tile*2+nh]
__device__ __align__(16) float          g_ploss[Sv];

// ---------------- fast exp2 on FMA pipe ----------------
__device__ __forceinline__ float fexp2(float x) {
    float z = __fadd_rn(x, 12582912.0f);
    float f = __fsub_rn(x, __fsub_rn(z, 12582912.0f));
    int   e = __float_as_int(z) << 23;
    float p = 1.3333558146e-3f;
    p = __fmaf_rn(p, f, 9.6181291918e-3f);
    p = __fmaf_rn(p, f, 5.5504108664e-2f);
    p = __fmaf_rn(p, f, 2.4022650696e-1f);
    p = __fmaf_rn(p, f, 6.9314718056e-1f);
    p = __fmaf_rn(p, f, 1.0f);
    return __int_as_float(__float_as_int(p) + e);
}

// ---------------- top-2 helpers (jax.lax.top_k tie semantics) ----------------
__device__ __forceinline__ bool better(float v, int i, float vx, int ix) {
    return v > vx || (v == vx && i < ix);
}
__device__ __forceinline__ void top2upd(float v, int pidx, float& v1, int& j1, float& v2, int& j2) {
    if (better(v, pidx, v1, j1)) { v2=v1; j2=j1; v1=v; j1=pidx; }
    else if (better(v, pidx, v2, j2)) { v2=v; j2=pidx; }
}

// ---------------- K1 (fused pre): flat table + iou bits + per-half top-2 ----------------
__global__ __launch_bounds__(256) void k_pre(const float* __restrict__ iou2d,
                                             const float* __restrict__ iou2ds) {
    __shared__ float scv[16];
    __shared__ int   sci[16];
    int bid = blockIdx.x, t = threadIdx.x;

    if (bid < 64) {
        int idx = bid*256 + t;
        int i = idx >> 7, j = idx & 127;
        if (j >= i) g_flat[i*Nn - (i*(i-1))/2 + (j - i)] = idx;
        return;
    }
    if (bid < 64 + 2048) {
        int r = bid - 64;
        int s = r >> 6;
        int idx = (r & 63)*256 + t;
        int i = idx >> 7, j = idx & 127;
        if (j >= i) {
            int p = i*Nn - (i*(i-1))/2 + (j - i);
            g_iou[s*Pn + p] = (iou2d[(size_t)s*NNe + idx] > 0.5f) ? 1 : 0;
        }
        return;
    }
    int r = bid - 2112;
    int m = r >> 1, half = r & 1;
    int w = t >> 5, l = t & 31;
    const float4* row = reinterpret_cast<const float4*>(iou2ds + (size_t)m*NNe);

    float4 f[8];
    int vb = half*2048 + t;
    #pragma unroll
    for (int it = 0; it < 8; it++) f[it] = row[vb + it*256];

    float v1 = -1e30f, v2 = -1e30f; int j1 = 0x7fffffff, j2 = 0x7fffffff;
    #pragma unroll
    for (int it = 0; it < 8; it++) {
        int flat = (vb + it*256)*4;
        #pragma unroll
        for (int qq = 0; qq < 4; qq++) {
            float v = (qq==0)?f[it].x:(qq==1)?f[it].y:(qq==2)?f[it].z:f[it].w;
            int fl = flat + qq;
            int i = fl >> 7, j = fl & 127;
            bool valid = (j >= i);
            int p = i*Nn - (i*(i-1))/2 + (j - i);
            top2upd(valid ? v : -1e30f, valid ? p : 0x7fffffff, v1, j1, v2, j2);
        }
    }
    #pragma unroll
    for (int off = 16; off > 0; off >>= 1) {
        float o1 = __shfl_xor_sync(0xffffffffu, v1, off);
        int   oj1= __shfl_xor_sync(0xffffffffu, j1, off);
        float o2 = __shfl_xor_sync(0xffffffffu, v2, off);
        int   oj2= __shfl_xor_sync(0xffffffffu, j2, off);
        if (better(o1, oj1, v1, j1)) {
            if (better(v1, j1, o2, oj2)) { v2=v1; j2=j1; } else { v2=o2; j2=oj2; }
            v1=o1; j1=oj1;
        } else if (better(o1, oj1, v2, j2)) { v2=o1; j2=oj1; }
    }
    if (l == 0) { scv[w*2]=v1; sci[w*2]=j1; scv[w*2+1]=v2; sci[w*2+1]=j2; }
    __syncthreads();
    if (t == 0) {
        float b1=-1e30f, b2=-1e30f; int bi1=0x7fffffff, bi2=0x7fffffff;
        #pragma unroll
        for (int e = 0; e < 16; e++) top2upd(scv[e], sci[e], b1, bi1, b2, bi2);
        g_cv[m*16 + half*2]     = b1; g_ci[m*16 + half*2]     = bi1;
        g_cv[m*16 + half*2 + 1] = b2; g_ci[m*16 + half*2 + 1] = bi2;
    }
}

// ---------------- K2: gather + L2 norm + bf16 emit ----------------
__global__ __launch_bounds__(256) void k_norm(const float* __restrict__ vf) {
    __shared__ float tile[32*257];
    __shared__ float ssb[8][32];
    __shared__ float sinv[32];
    int b = blockIdx.y, p0 = blockIdx.x*32, t = threadIdx.x;
    int p = t & 31, c0 = t >> 5;
    int fi = g_flat[p0 + p];
    const float* base = vf + (size_t)b*Cc*NNe + fi;
    float ss = 0.f;
    #pragma unroll
    for (int k = 0; k < 32; k++) {
        int c = c0*32 + k;
        float v = base[(size_t)c*NNe];
        tile[p*257 + c] = v;
        ss += v*v;
    }
    ssb[c0][p] = ss;
    __syncthreads();
    if (t < 32) {
        float tot = 0.f;
        #pragma unroll
        for (int k = 0; k < 8; k++) tot += ssb[k][t];
        float inv = 1.0f / fmaxf(sqrtf(tot), 1e-12f);
        sinv[t] = inv;
        g_inv[b*Pn + p0 + t] = inv;
    }
    __syncthreads();
    int rowbase = b*Pn + p0;
    #pragma unroll
    for (int it = 0; it < 16; it++) {
        int id = it*256 + t;
        int pr = id >> 7, c2 = (id & 127)*2;
        float inv = sinv[pr];
        __nv_bfloat162 h = __floats2bfloat162_rn(tile[pr*257+c2]*inv, tile[pr*257+c2+1]*inv);
        *reinterpret_cast<__nv_bfloat162*>(g_vfb + (size_t)(rowbase+pr)*Cc + c2) = h;
    }
}

// ---------------- K3: merge candidates + build pos rows (fragment-major A) ----------------
__global__ __launch_bounds__(256) void k_pos(const float* __restrict__ vf) {
    __shared__ int sj;
    int r = blockIdx.x, c = threadIdx.x;
    int m = r >> 1, k = r & 1;
    if (c == 0) {
        float v1=-1e30f, v2=-1e30f; int j1=0x7fffffff, j2=0x7fffffff;
        #pragma unroll
        for (int e = 0; e < 4; e++) {
            float v = g_cv[m*16 + e]; int i = g_ci[m*16 + e];
            if (better(v, i, v1, j1)) { v2=v1; j2=j1; v1=v; j1=i; }
            else if (better(v, i, v2, j2)) { v2=v; j2=i; }
        }
        sj = k ? j2 : j1;
    }
    __syncthreads();
    int j = sj;
    int b = m >> 3;
    int row = b*Pn + j;
    __nv_bfloat16 hv = g_vfb[(size_t)row*Cc + c];
    g_posf[r*Cc + c] = vf[((size_t)b*Cc + c)*NNe + g_flat[j]] * g_inv[row];

    // fragment-major store: word (c/2) -> (ks, cb, chalf); row r -> (mq, mt, lanerow, ahalf)
    unsigned short us = __bfloat16_as_ushort(hv);
    unsigned mine = us;
    unsigned hi = __shfl_down_sync(0xffffffffu, mine, 1);
    if ((c & 1) == 0) {
        unsigned pair = mine | (hi << 16);
        int word = c >> 1;
        int ks = word >> 3, wd8 = word & 7;
        int cb = wd8 & 3, chalf = wd8 >> 2;
        int mq = r >> 5, mt = (r >> 4) & 1, rr = r & 15;
        int lanerow = rr & 7, ahalf = rr >> 3;
        int lane = lanerow*4 + cb;
        int comp = ahalf + chalf*2;
        g_posfr[((((mq*2 + mt)*16 + ks)*32) + lane)*4 + comp] = pair;
    }
}

// ---------------- K4: persistent GEMM, split-N 8 warps (32 rows x 16 cols each) ----------------
__device__ __forceinline__ void ldm4(unsigned addr, unsigned &r0, unsigned &r1, unsigned &r2, unsigned &r3) {
    asm volatile("ldmatrix.sync.aligned.m8n8.x4.shared.b16 {%0,%1,%2,%3}, [%4];"
                 : "=r"(r0), "=r"(r1), "=r"(r2), "=r"(r3) : "r"(addr));
}
__device__ __forceinline__ void mma16816(float* c, unsigned a0, unsigned a1, unsigned a2, unsigned a3,
                                         unsigned b0, unsigned b1) {
    asm volatile("mma.sync.aligned.m16n8k16.row.col.f32.bf16.bf16.f32 "
                 "{%0,%1,%2,%3}, {%4,%5,%6,%7}, {%8,%9}, {%0,%1,%2,%3};"
                 : "+f"(c[0]), "+f"(c[1]), "+f"(c[2]), "+f"(c[3])
                 : "r"(a0), "r"(a1), "r"(a2), "r"(a3), "r"(b0), "r"(b1));
}
__device__ __forceinline__ void cp16(unsigned saddr, const void* gaddr) {
    asm volatile("cp.async.cg.shared.global [%0], [%1], 16;" :: "r"(saddr), "l"(gaddr));
}

__global__ __launch_bounds__(256, 2) void k_gemm() {
    __shared__ __align__(16) __nv_bfloat16 sB[2][32*256];   // 2 x 16KB
    __shared__ unsigned char sI[2][128];                     // 4 sent x 32 cols

    int t = threadIdx.x;
    int w = t >> 5, l = t & 31;
    int mq = w & 3;          // M quarter: rows mq*32 .. +32
    int nh = w >> 2;         // N half: cols nh*16 .. +16
    unsigned sb0 = (unsigned)__cvta_generic_to_shared(&sB[0][0]);

    const uint4* gF = reinterpret_cast<const uint4*>(g_posfr);
    int fb0 = ((mq*2 + 0)*16)*32 + l;   // fragment base, mt=0
    int fb1 = ((mq*2 + 1)*16)*32 + l;   // mt=1

    // preload A half 0 (ks 0..7)
    unsigned af[8][2][4];
    #pragma unroll
    for (int kk = 0; kk < 8; kk++) {
        uint4 v0 = gF[fb0 + kk*32];
        uint4 v1 = gF[fb1 + kk*32];
        af[kk][0][0]=v0.x; af[kk][0][1]=v0.y; af[kk][0][2]=v0.z; af[kk][0][3]=v0.w;
        af[kk][1][0]=v1.x; af[kk][1][1]=v1.y; af[kk][1][2]=v1.z; af[kk][1][3]=v1.w;
    }

    // prefetch first tile
    int tile0 = blockIdx.x;
    {
        const char* gB = reinterpret_cast<const char*>(g_vfb + (size_t)tile0*32*Cc);
        #pragma unroll
        for (int it = 0; it < 4; it++) {
            int idx = it*256 + t;
            int row = idx >> 5, ch = idx & 31;
            cp16(sb0 + (row*32 + (ch ^ (row & 7)))*16, gB + row*512 + ch*16);
        }
        if (t < 128) {
            int b0v = (tile0*32)/Pn, j00 = tile0*32 - b0v*Pn;
            sI[0][t] = g_iou[(b0v*4 + (t >> 5))*Pn + j00 + (t & 31)];
        }
        asm volatile("cp.async.commit_group;");
    }

    int rowBbase = nh*16 + (l & 7) + ((l >> 4) & 1) * 8;
    unsigned rowOff = rowBbase * 512;
    int rowSw = rowBbase & 7;
    int chSelB = (l >> 3) & 1;
    const float K2E = 14.4269504088896340f;
    int nb = (l & 3) * 2;

    int loaded = 0;   // which A half is in registers
    int cur = 0;
    for (int tile = tile0; tile < NT2; tile += GRID) {
        int ntile = tile + GRID;
        bool hn = ntile < NT2;
        if (hn) {
            const char* gB = reinterpret_cast<const char*>(g_vfb + (size_t)ntile*32*Cc);
            unsigned base = sb0 + (cur ^ 1)*16384;
            #pragma unroll
            for (int it = 0; it < 4; it++) {
                int idx = it*256 + t;
                int row = idx >> 5, ch = idx & 31;
                cp16(base + (row*32 + (ch ^ (row & 7)))*16, gB + row*512 + ch*16);
            }
            if (t < 128) {
                int bn = (ntile*32)/Pn, j0n = ntile*32 - bn*Pn;
                sI[cur ^ 1][t] = g_iou[(bn*4 + (t >> 5))*Pn + j0n + (t & 31)];
            }
            asm volatile("cp.async.commit_group;");
            asm volatile("cp.async.wait_group 1;");
        } else {
            asm volatile("cp.async.wait_group 0;");
        }
        __syncthreads();

        int b = (tile*32)/Pn;
        unsigned sb = sb0 + cur*16384;
        const unsigned char* sIc = sI[cur];

        float acc[2][2][4];     // [mt][nt][quad]
        #pragma unroll
        for (int mt = 0; mt < 2; mt++)
            #pragma unroll
            for (int i = 0; i < 2; i++)
                #pragma unroll
                for (int q = 0; q < 4; q++) acc[mt][i][q] = 0.f;

        int h0 = loaded, h1 = loaded ^ 1;
        // first half: use resident af, reload af[kk] for other half right after last use
        #pragma unroll
        for (int kk = 0; kk < 8; kk++) {
            int chB = 2*(h0*8 + kk) + chSelB;
            unsigned b0, b1, b2, b3;
            ldm4(sb + rowOff + (((chB ^ rowSw) & 31) << 4), b0, b1, b2, b3);
            #pragma unroll
            for (int mt = 0; mt < 2; mt++) {
                mma16816(acc[mt][0], af[kk][mt][0], af[kk][mt][1], af[kk][mt][2], af[kk][mt][3], b0, b1);
                mma16816(acc[mt][1], af[kk][mt][0], af[kk][mt][1], af[kk][mt][2], af[kk][mt][3], b2, b3);
            }
            uint4 v0 = gF[fb0 + (h1*8 + kk)*32];
            uint4 v1 = gF[fb1 + (h1*8 + kk)*32];
            af[kk][0][0]=v0.x; af[kk][0][1]=v0.y; af[kk][0][2]=v0.z; af[kk][0][3]=v0.w;
            af[kk][1][0]=v1.x; af[kk][1][1]=v1.y; af[kk][1][2]=v1.z; af[kk][1][3]=v1.w;
        }
        // second half with freshly loaded af
        #pragma unroll
        for (int kk = 0; kk < 8; kk++) {
            int chB = 2*(h1*8 + kk) + chSelB;
            unsigned b0, b1, b2, b3;
            ldm4(sb + rowOff + (((chB ^ rowSw) & 31) << 4), b0, b1, b2, b3);
            #pragma unroll
            for (int mt = 0; mt < 2; mt++) {
                mma16816(acc[mt][0], af[kk][mt][0], af[kk][mt][1], af[kk][mt][2], af[kk][mt][3], b0, b1);
                mma16816(acc[mt][1], af[kk][mt][0], af[kk][mt][1], af[kk][mt][2], af[kk][mt][3], b2, b3);
            }
        }
        loaded = h1;

        // epilogue: exp(dot/T) with neg mask, per-row partial sums (cols = nh half)
        #pragma unroll
        for (int mt = 0; mt < 2; mt++) {
            int rLo = mq*32 + mt*16 + (l >> 2), rHi = rLo + 8;
            bool own = ((mq*2 + mt) == b);
            int siLo = ((rLo >> 2) & 3) * 32, siHi = ((rHi >> 2) & 3) * 32;
            float sumLo = 0.f, sumHi = 0.f;
            #pragma unroll
            for (int nt2 = 0; nt2 < 2; nt2++) {
                #pragma unroll
                for (int q = 0; q < 2; q++) {
                    int n = nh*16 + nt2*8 + nb + q;
                    float eLo = fexp2(acc[mt][nt2][q]   * K2E);
                    float eHi = fexp2(acc[mt][nt2][2+q] * K2E);
                    bool mLo = own && sIc[siLo + n];
                    bool mHi = own && sIc[siHi + n];
                    sumLo += mLo ? 0.f : eLo;
                    sumHi += mHi ? 0.f : eHi;
                }
            }
            sumLo += __shfl_xor_sync(0xffffffffu, sumLo, 1);
            sumLo += __shfl_xor_sync(0xffffffffu, sumLo, 2);
            sumHi += __shfl_xor_sync(0xffffffffu, sumHi, 1);
            sumHi += __shfl_xor_sync(0xffffffffu, sumHi, 2);
            if ((l & 3) == 0) {
                g_partial[(size_t)rLo*PW + tile*2 + nh] = sumLo;
                g_partial[(size_t)rHi*PW + tile*2 + nh] = sumHi;
            }
        }
        __syncthreads();
        cur ^= 1;
    }
}

// ---------------- K5: negsum reduce + per-sentence pair terms (fused) ----------------
__global__ __launch_bounds__(128) void k_pairs() {
    __shared__ float sp[4*256];
    __shared__ float sneg[4];
    __shared__ float terms[16];
    int s = blockIdx.x, t = threadIdx.x;
    int w = t >> 5, l = t & 31;

    for (int i = t; i < 1024; i += 128) sp[i] = g_posf[s*1024 + i];

    {
        const float* prow = g_partial + (size_t)(s*4 + w)*PW;
        float acc = 0.f;
        for (int k = l; k < PW; k += 32) acc += prow[k];
        #pragma unroll
        for (int off = 16; off > 0; off >>= 1) acc += __shfl_xor_sync(0xffffffffu, acc, off);
        if (l == 0) sneg[w] = acc;
    }
    __syncthreads();

    int pair = t >> 3, cc = t & 7;
    int a_ref = pair >> 2, a_pos = pair & 3;
    float d = 0.f;
    #pragma unroll
    for (int k = 0; k < 32; k++) {
        int c = cc*32 + k;
        d += sp[a_ref*256 + c] * sp[a_pos*256 + c];
    }
    d += __shfl_xor_sync(0xffffffffu, d, 1);
    d += __shfl_xor_sync(0xffffffffu, d, 2);
    d += __shfl_xor_sync(0xffffffffu, d, 4);
    if (cc == 0) {
        float x = d * 10.0f;
        float ns = sneg[a_ref];
        terms[pair] = -(x - logf(expf(x) + ns));
    }
    __syncthreads();
    if (t == 0) {
        float su = 0.f;
        #pragma unroll
        for (int i = 0; i < 16; i++) su += terms[i];
        g_ploss[s] = su;
    }
}

// ---------------- K6: final mean ----------------
__global__ void k_final(float* out) {
    if (threadIdx.x == 0) {
        float su = 0.f;
        #pragma unroll
        for (int i = 0; i < Sv; i++) su += g_ploss[i];
        out[0] = su * (1.0f / 512.0f);
    }
}

// ---------------- launch ----------------
extern "C" void kernel_launch(void* const* d_in, const int* in_sizes, int n_in,
                              void* d_out, int out_size) {
    const float* video  = (const float*)d_in[0];
    const float* iou2d  = (const float*)d_in[4];
    const float* iou2ds = (const float*)d_in[5];
    float* out = (float*)d_out;

    k_pre<<<2240, 256>>>(iou2d, iou2ds);
    k_norm<<<dim3(Pn/32, Bv), 256>>>(video);
    k_pos<<<RT, 256>>>(video);
    k_gemm<<<GRID, 256>>>();     // 4th launch -> profiled
    k_pairs<<<Sv, 128>>>();
    k_final<<<1, 32>>>(out);
}

// round 14
// speedup vs baseline: 1.0520x; 1.0520x over previous
#include <cuda_runtime.h>
#include <cuda_bf16.h>
#include <math.h>

// ---------------- problem constants ----------------
constexpr int Bv   = 8;      // videos
constexpr int Cc   = 256;    // feature dim
constexpr int Nn   = 128;    // N
constexpr int NNe  = Nn*Nn;  // 16384
constexpr int Sv   = 32;     // sentences
constexpr int Mv   = 64;     // moments
constexpr int Pn   = 8256;   // N*(N+1)/2 proposals
constexpr int BP   = Bv*Pn;  // 66048
constexpr int RT   = 128;    // pos rows = M*K
constexpr int NT2  = BP/32;  // 2064 GEMM column tiles (32 | Pn)
constexpr int GRID = 296;    // persistent GEMM CTAs (2 per SM x 148)

// ---------------- scratch ----------------
__device__ __align__(16) int            g_flat[Pn];
__device__ __align__(16) float          g_inv[BP];
__device__ __align__(16) __nv_bfloat16  g_vfb[(size_t)BP*Cc];
__device__ __align__(16) unsigned char  g_iou[Sv*Pn];
__device__ __align__(16) float          g_cv[Mv*16];
__device__ __align__(16) int            g_ci[Mv*16];
__device__ __align__(16) __nv_bfloat16  g_posb[RT*Cc];
__device__ __align__(16) float          g_posf[RT*Cc];
__device__ __align__(16) float          g_partial[(size_t)RT*NT2];   // [row][tile]
__device__ __align__(16) float          g_ploss[Sv];

// ---------------- fast exp2 on FMA pipe ----------------
__device__ __forceinline__ float fexp2(float x) {
    float z = __fadd_rn(x, 12582912.0f);
    float f = __fsub_rn(x, __fsub_rn(z, 12582912.0f));
    int   e = __float_as_int(z) << 23;
    float p = 1.3333558146e-3f;
    p = __fmaf_rn(p, f, 9.6181291918e-3f);
    p = __fmaf_rn(p, f, 5.5504108664e-2f);
    p = __fmaf_rn(p, f, 2.4022650696e-1f);
    p = __fmaf_rn(p, f, 6.9314718056e-1f);
    p = __fmaf_rn(p, f, 1.0f);
    return __int_as_float(__float_as_int(p) + e);
}

// exact inverse of the upper-tri flattening: p -> triangle row i
__device__ __forceinline__ int row_of_p(int p) {
    float disc = 66049.0f - 8.0f * (float)p;          // (257-2i)^2 at row starts: exact in fp32
    int i = (int)((257.0f - sqrtf(disc)) * 0.5f);
    while (i*Nn - (i*(i-1))/2 > p) i--;
    while ((i+1)*Nn - ((i+1)*i)/2 <= p) i++;
    return i;
}

// ---------------- top-2 helpers (jax.lax.top_k tie semantics) ----------------
__device__ __forceinline__ bool better(float v, int i, float vx, int ix) {
    return v > vx || (v == vx && i < ix);
}
__device__ __forceinline__ void top2upd(float v, int pidx, float& v1, int& j1, float& v2, int& j2) {
    if (better(v, pidx, v1, j1)) { v2=v1; j2=j1; v1=v; j1=pidx; }
    else if (better(v, pidx, v2, j2)) { v2=v; j2=pidx; }
}

// ---------------- K-pre (stream 2): flat table + iou bits + per-half top-2 ----------------
__global__ __launch_bounds__(256) void k_pre(const float* __restrict__ iou2d,
                                             const float* __restrict__ iou2ds) {
    __shared__ float scv[16];
    __shared__ int   sci[16];
    int bid = blockIdx.x, t = threadIdx.x;

    if (bid < 64) {
        int idx = bid*256 + t;
        int i = idx >> 7, j = idx & 127;
        if (j >= i) g_flat[i*Nn - (i*(i-1))/2 + (j - i)] = idx;
        return;
    }
    if (bid < 64 + 2048) {
        int r = bid - 64;
        int s = r >> 6;
        int idx = (r & 63)*256 + t;
        int i = idx >> 7, j = idx & 127;
        if (j >= i) {
            int p = i*Nn - (i*(i-1))/2 + (j - i);
            g_iou[s*Pn + p] = (iou2d[(size_t)s*NNe + idx] > 0.5f) ? 1 : 0;
        }
        return;
    }
    int r = bid - 2112;
    int m = r >> 1, half = r & 1;
    int w = t >> 5, l = t & 31;
    const float4* row = reinterpret_cast<const float4*>(iou2ds + (size_t)m*NNe);

    float4 f[8];
    int vb = half*2048 + t;
    #pragma unroll
    for (int it = 0; it < 8; it++) f[it] = row[vb + it*256];

    float v1 = -1e30f, v2 = -1e30f; int j1 = 0x7fffffff, j2 = 0x7fffffff;
    #pragma unroll
    for (int it = 0; it < 8; it++) {
        int flat = (vb + it*256)*4;
        #pragma unroll
        for (int qq = 0; qq < 4; qq++) {
            float v = (qq==0)?f[it].x:(qq==1)?f[it].y:(qq==2)?f[it].z:f[it].w;
            int fl = flat + qq;
            int i = fl >> 7, j = fl & 127;
            bool valid = (j >= i);
            int p = i*Nn - (i*(i-1))/2 + (j - i);
            top2upd(valid ? v : -1e30f, valid ? p : 0x7fffffff, v1, j1, v2, j2);
        }
    }
    #pragma unroll
    for (int off = 16; off > 0; off >>= 1) {
        float o1 = __shfl_xor_sync(0xffffffffu, v1, off);
        int   oj1= __shfl_xor_sync(0xffffffffu, j1, off);
        float o2 = __shfl_xor_sync(0xffffffffu, v2, off);
        int   oj2= __shfl_xor_sync(0xffffffffu, j2, off);
        if (better(o1, oj1, v1, j1)) {
            if (better(v1, j1, o2, oj2)) { v2=v1; j2=j1; } else { v2=o2; j2=oj2; }
            v1=o1; j1=oj1;
        } else if (better(o1, oj1, v2, j2)) { v2=o1; j2=oj1; }
    }
    if (l == 0) { scv[w*2]=v1; sci[w*2]=j1; scv[w*2+1]=v2; sci[w*2+1]=j2; }
    __syncthreads();
    if (t == 0) {
        float b1=-1e30f, b2=-1e30f; int bi1=0x7fffffff, bi2=0x7fffffff;
        #pragma unroll
        for (int e = 0; e < 16; e++) top2upd(scv[e], sci[e], b1, bi1, b2, bi2);
        g_cv[m*16 + half*2]     = b1; g_ci[m*16 + half*2]     = bi1;
        g_cv[m*16 + half*2 + 1] = b2; g_ci[m*16 + half*2 + 1] = bi2;
    }
}

// ---------------- K-norm (main stream): gather + L2 norm + bf16 emit ----------------
// no g_flat dependency: row computed in closed form -> can overlap with k_pre
__global__ __launch_bounds__(256) void k_norm(const float* __restrict__ vf) {
    __shared__ float tile[32*257];
    __shared__ float ssb[8][32];
    __shared__ float sinv[32];
    int b = blockIdx.y, p0 = blockIdx.x*32, t = threadIdx.x;
    int p = t & 31, c0 = t >> 5;
    int pp = p0 + p;
    int ri = row_of_p(pp);
    int fi = ri*Nn + (pp - (ri*Nn - (ri*(ri-1))/2) + ri);
    const float* base = vf + (size_t)b*Cc*NNe + fi;
    float ss = 0.f;
    #pragma unroll
    for (int k = 0; k < 32; k++) {
        int c = c0*32 + k;
        float v = base[(size_t)c*NNe];
        tile[p*257 + c] = v;
        ss += v*v;
    }
    ssb[c0][p] = ss;
    __syncthreads();
    if (t < 32) {
        float tot = 0.f;
        #pragma unroll
        for (int k = 0; k < 8; k++) tot += ssb[k][t];
        float inv = 1.0f / fmaxf(sqrtf(tot), 1e-12f);
        sinv[t] = inv;
        g_inv[b*Pn + p0 + t] = inv;
    }
    __syncthreads();
    int rowbase = b*Pn + p0;
    #pragma unroll
    for (int it = 0; it < 16; it++) {
        int id = it*256 + t;
        int pr = id >> 7, c2 = (id & 127)*2;
        float inv = sinv[pr];
        __nv_bfloat162 h = __floats2bfloat162_rn(tile[pr*257+c2]*inv, tile[pr*257+c2+1]*inv);
        *reinterpret_cast<__nv_bfloat162*>(g_vfb + (size_t)(rowbase+pr)*Cc + c2) = h;
    }
}

// ---------------- K-pos: merge candidates + build pos rows ----------------
__global__ __launch_bounds__(256) void k_pos(const float* __restrict__ vf) {
    __shared__ int sj;
    int r = blockIdx.x, c = threadIdx.x;
    int m = r >> 1, k = r & 1;
    if (c == 0) {
        float v1=-1e30f, v2=-1e30f; int j1=0x7fffffff, j2=0x7fffffff;
        #pragma unroll
        for (int e = 0; e < 4; e++) {
            float v = g_cv[m*16 + e]; int i = g_ci[m*16 + e];
            if (better(v, i, v1, j1)) { v2=v1; j2=j1; v1=v; j1=i; }
            else if (better(v, i, v2, j2)) { v2=v; j2=i; }
        }
        sj = k ? j2 : j1;
    }
    __syncthreads();
    int j = sj;
    int b = m >> 3;
    int row = b*Pn + j;
    g_posb[r*Cc + c] = g_vfb[(size_t)row*Cc + c];
    g_posf[r*Cc + c] = vf[((size_t)b*Cc + c)*NNe + g_flat[j]] * g_inv[row];
}

// ---------------- K-gemm: persistent mma.sync, 4 warps x 32 rows (best measured) ----------------
__device__ __forceinline__ void ldm4(unsigned addr, unsigned &r0, unsigned &r1, unsigned &r2, unsigned &r3) {
    asm volatile("ldmatrix.sync.aligned.m8n8.x4.shared.b16 {%0,%1,%2,%3}, [%4];"
                 : "=r"(r0), "=r"(r1), "=r"(r2), "=r"(r3) : "r"(addr));
}
__device__ __forceinline__ void mma16816(float* c, unsigned a0, unsigned a1, unsigned a2, unsigned a3,
                                         unsigned b0, unsigned b1) {
    asm volatile("mma.sync.aligned.m16n8k16.row.col.f32.bf16.bf16.f32 "
                 "{%0,%1,%2,%3}, {%4,%5,%6,%7}, {%8,%9}, {%0,%1,%2,%3};"
                 : "+f"(c[0]), "+f"(c[1]), "+f"(c[2]), "+f"(c[3])
                 : "r"(a0), "r"(a1), "r"(a2), "r"(a3), "r"(b0), "r"(b1));
}
__device__ __forceinline__ void cp16(unsigned saddr, const void* gaddr) {
    asm volatile("cp.async.cg.shared.global [%0], [%1], 16;" :: "r"(saddr), "l"(gaddr));
}

__global__ __launch_bounds__(128, 2) void k_gemm() {
    __shared__ __align__(16) __nv_bfloat16 sB[2][32*256];   // 2 x 16KB
    __shared__ unsigned char sI[2][128];                     // 4 sent x 32 cols

    int t = threadIdx.x;
    int w = t >> 5, l = t & 31;
    unsigned sb0 = (unsigned)__cvta_generic_to_shared(&sB[0][0]);

    // A fragments once per persistent CTA: warp w owns M rows [w*32, w*32+32)
    const unsigned* gA = reinterpret_cast<const unsigned*>(g_posb);
    int cb = l & 3;
    unsigned af[16][2][4];
    #pragma unroll
    for (int ks = 0; ks < 16; ks++) {
        #pragma unroll
        for (int mt = 0; mt < 2; mt++) {
            int ra = w*32 + mt*16 + (l >> 2);
            int col = ks*8 + cb;
            af[ks][mt][0] = gA[ra*128 + col];
            af[ks][mt][1] = gA[(ra+8)*128 + col];
            af[ks][mt][2] = gA[ra*128 + col + 4];
            af[ks][mt][3] = gA[(ra+8)*128 + col + 4];
        }
    }

    // prefetch first tile
    int tile0 = blockIdx.x;
    {
        const char* gB = reinterpret_cast<const char*>(g_vfb + (size_t)tile0*32*Cc);
        #pragma unroll
        for (int it = 0; it < 8; it++) {
            int idx = it*128 + t;
            int row = idx >> 5, ch = idx & 31;
            cp16(sb0 + (row*32 + (ch ^ (row & 7)))*16, gB + row*512 + ch*16);
        }
        int b0v = (tile0*32)/Pn, j00 = tile0*32 - b0v*Pn;
        sI[0][t] = g_iou[(b0v*4 + (t >> 5))*Pn + j00 + (t & 31)];
        asm volatile("cp.async.commit_group;");
    }

    int rowBbase = (l & 7) + ((l >> 4) & 1) * 8;
    int chSelB   = (l >> 3) & 1;
    const float K2E = 14.4269504088896340f;
    int mr = l >> 2;
    int nb = (l & 3) * 2;

    int cur = 0;
    for (int tile = tile0; tile < NT2; tile += GRID) {
        int nt = tile + GRID;
        bool hn = nt < NT2;
        if (hn) {
            const char* gB = reinterpret_cast<const char*>(g_vfb + (size_t)nt*32*Cc);
            unsigned base = sb0 + (cur ^ 1)*16384;
            #pragma unroll
            for (int it = 0; it < 8; it++) {
                int idx = it*128 + t;
                int row = idx >> 5, ch = idx & 31;
                cp16(base + (row*32 + (ch ^ (row & 7)))*16, gB + row*512 + ch*16);
            }
            int bn = (nt*32)/Pn, j0n = nt*32 - bn*Pn;
            sI[cur ^ 1][t] = g_iou[(bn*4 + (t >> 5))*Pn + j0n + (t & 31)];
            asm volatile("cp.async.commit_group;");
            asm volatile("cp.async.wait_group 1;");
        } else {
            asm volatile("cp.async.wait_group 0;");
        }
        __syncthreads();

        int b = (tile*32)/Pn;
        unsigned sb = sb0 + cur*16384;
        const unsigned char* sIc = sI[cur];

        float acc[2][4][4];
        #pragma unroll
        for (int mt = 0; mt < 2; mt++)
            #pragma unroll
            for (int i = 0; i < 4; i++)
                #pragma unroll
                for (int q = 0; q < 4; q++) acc[mt][i][q] = 0.f;

        #pragma unroll
        for (int ks = 0; ks < 16; ks++) {
            #pragma unroll
            for (int ntp = 0; ntp < 2; ntp++) {
                int rowB = ntp*16 + rowBbase;
                int chB  = 2*ks + chSelB;
                unsigned b0, b1, b2, b3;
                ldm4(sb + rowB*512 + (((chB ^ (rowB & 7)) & 31) << 4), b0, b1, b2, b3);
                #pragma unroll
                for (int mt = 0; mt < 2; mt++) {
                    mma16816(acc[mt][ntp*2],     af[ks][mt][0], af[ks][mt][1], af[ks][mt][2], af[ks][mt][3], b0, b1);
                    mma16816(acc[mt][ntp*2 + 1], af[ks][mt][0], af[ks][mt][1], af[ks][mt][2], af[ks][mt][3], b2, b3);
                }
            }
        }

        // epilogue: exp(dot/T) with neg mask, per-row partial sums
        #pragma unroll
        for (int mt = 0; mt < 2; mt++) {
            int rLo = w*32 + mt*16 + mr, rHi = rLo + 8;
            bool own = ((2*w + mt) == b);
            int siLo = ((rLo >> 2) & 3) * 32, siHi = ((rHi >> 2) & 3) * 32;
            float sumLo = 0.f, sumHi = 0.f;
            #pragma unroll
            for (int nt2 = 0; nt2 < 4; nt2++) {
                #pragma unroll
                for (int q = 0; q < 2; q++) {
                    int n = nt2*8 + nb + q;
                    float eLo = fexp2(acc[mt][nt2][q]   * K2E);
                    float eHi = fexp2(acc[mt][nt2][2+q] * K2E);
                    bool mLo = own && sIc[siLo + n];
                    bool mHi = own && sIc[siHi + n];
                    sumLo += mLo ? 0.f : eLo;
                    sumHi += mHi ? 0.f : eHi;
                }
            }
            sumLo += __shfl_xor_sync(0xffffffffu, sumLo, 1);
            sumLo += __shfl_xor_sync(0xffffffffu, sumLo, 2);
            sumHi += __shfl_xor_sync(0xffffffffu, sumHi, 1);
            sumHi += __shfl_xor_sync(0xffffffffu, sumHi, 2);
            if ((l & 3) == 0) {
                g_partial[(size_t)rLo*NT2 + tile] = sumLo;
                g_partial[(size_t)rHi*NT2 + tile] = sumHi;
            }
        }
        __syncthreads();
        cur ^= 1;
    }
}

// ---------------- K-pairs: negsum reduce + per-sentence pair terms (fused) ----------------
__global__ __launch_bounds__(128) void k_pairs() {
    __shared__ float sp[4*256];
    __shared__ float sneg[4];
    __shared__ float terms[16];
    int s = blockIdx.x, t = threadIdx.x;
    int w = t >> 5, l = t & 31;

    for (int i = t; i < 1024; i += 128) sp[i] = g_posf[s*1024 + i];

    {
        const float* prow = g_partial + (size_t)(s*4 + w)*NT2;
        float acc = 0.f;
        for (int k = l; k < NT2; k += 32) acc += prow[k];
        #pragma unroll
        for (int off = 16; off > 0; off >>= 1) acc += __shfl_xor_sync(0xffffffffu, acc, off);
        if (l == 0) sneg[w] = acc;
    }
    __syncthreads();

    int pair = t >> 3, cc = t & 7;
    int a_ref = pair >> 2, a_pos = pair & 3;
    float d = 0.f;
    #pragma unroll
    for (int k = 0; k < 32; k++) {
        int c = cc*32 + k;
        d += sp[a_ref*256 + c] * sp[a_pos*256 + c];
    }
    d += __shfl_xor_sync(0xffffffffu, d, 1);
    d += __shfl_xor_sync(0xffffffffu, d, 2);
    d += __shfl_xor_sync(0xffffffffu, d, 4);
    if (cc == 0) {
        float x = d * 10.0f;
        float ns = sneg[a_ref];
        terms[pair] = -(x - logf(expf(x) + ns));
    }
    __syncthreads();
    if (t == 0) {
        float su = 0.f;
        #pragma unroll
        for (int i = 0; i < 16; i++) su += terms[i];
        g_ploss[s] = su;
    }
}

// ---------------- K-final: mean ----------------
__global__ void k_final(float* out) {
    if (threadIdx.x == 0) {
        float su = 0.f;
        #pragma unroll
        for (int i = 0; i < Sv; i++) su += g_ploss[i];
        out[0] = su * (1.0f / 512.0f);
    }
}

// ---------------- launch: fork k_pre onto a side stream, overlap with k_norm ----------------
extern "C" void kernel_launch(void* const* d_in, const int* in_sizes, int n_in,
                              void* d_out, int out_size) {
    const float* video  = (const float*)d_in[0];
    const float* iou2d  = (const float*)d_in[4];
    const float* iou2ds = (const float*)d_in[5];
    float* out = (float*)d_out;

    cudaStream_t s2;
    cudaEvent_t evFork, evJoin;
    cudaStreamCreateWithFlags(&s2, cudaStreamNonBlocking);
    cudaEventCreateWithFlags(&evFork, cudaEventDisableTiming);
    cudaEventCreateWithFlags(&evJoin, cudaEventDisableTiming);

    // fork: side branch runs k_pre while main stream runs k_norm
    cudaEventRecord(evFork, 0);
    cudaStreamWaitEvent(s2, evFork, 0);
    k_pre<<<2240, 256, 0, s2>>>(iou2d, iou2ds);
    k_norm<<<dim3(Pn/32, Bv), 256>>>(video);
    // join
    cudaEventRecord(evJoin, s2);
    cudaStreamWaitEvent(0, evJoin, 0);

    k_pos<<<RT, 256>>>(video);
    k_gemm<<<GRID, 128>>>();
    k_pairs<<<Sv, 128>>>();
    k_final<<<1, 32>>>(out);
    // note: s2/events intentionally not destroyed here — capture on the main
    // stream is still in progress; destroying mid-capture would invalidate it.
}